// round 2
// baseline (speedup 1.0000x reference)
#include <cuda_runtime.h>

// Half-lattice hop operator:
//   out = DIAG*psi - 0.5 * sum_mu ( K_fwd[mu] @ psi(fwd nbr) + K_bwd[mu] @ psi(bwd nbr) )
// T=Z=Y=16, X/2=8, D=12 complex. mu<3: periodic roll; mu=3: parity-gated X hop.

#define DD 12
#define NV (16*16*16*8)   // 32768 sites
#define DIAGC 4.5f
#define KSTRIDE ((size_t)NV * DD * DD)

__device__ __forceinline__ void cmatvec_row(
    const float* __restrict__ Kr, const float* __restrict__ Ki,
    const float* __restrict__ pr, const float* __restrict__ pi,
    float& hr0, float& hi0, float& hr1, float& hi1)
{
    const float4* kr4 = reinterpret_cast<const float4*>(Kr);
    const float4* ki4 = reinterpret_cast<const float4*>(Ki);
    const float4* pr4 = reinterpret_cast<const float4*>(pr);
    const float4* pi4 = reinterpret_cast<const float4*>(pi);
#pragma unroll
    for (int c = 0; c < 3; ++c) {
        float4 kr = __ldg(kr4 + c);
        float4 ki = __ldg(ki4 + c);
        float4 vr = __ldg(pr4 + c);
        float4 vi = __ldg(pi4 + c);
        // split across two accumulator pairs to shorten dependency chains
        hr0 = fmaf(kr.x, vr.x, hr0); hr0 = fmaf(-ki.x, vi.x, hr0);
        hi0 = fmaf(kr.x, vi.x, hi0); hi0 = fmaf( ki.x, vr.x, hi0);
        hr1 = fmaf(kr.y, vr.y, hr1); hr1 = fmaf(-ki.y, vi.y, hr1);
        hi1 = fmaf(kr.y, vi.y, hi1); hi1 = fmaf( ki.y, vr.y, hi1);
        hr0 = fmaf(kr.z, vr.z, hr0); hr0 = fmaf(-ki.z, vi.z, hr0);
        hi0 = fmaf(kr.z, vi.z, hi0); hi0 = fmaf( ki.z, vr.z, hi0);
        hr1 = fmaf(kr.w, vr.w, hr1); hr1 = fmaf(-ki.w, vi.w, hr1);
        hi1 = fmaf(kr.w, vi.w, hi1); hi1 = fmaf( ki.w, vr.w, hi1);
    }
}

__global__ __launch_bounds__(192, 8)
void hop_kernel(const float* __restrict__ psr, const float* __restrict__ psi,
                const float* __restrict__ Kfr, const float* __restrict__ Kfi,
                const float* __restrict__ Kbr, const float* __restrict__ Kbi,
                float* __restrict__ out)
{
    const int site = blockIdx.x * 16 + threadIdx.y;
    const int i = threadIdx.x;   // 0..11, output row

    float hr0 = 0.f, hi0 = 0.f, hr1 = 0.f, hi1 = 0.f;
    const size_t rowoff = (size_t)site * (DD * DD) + (size_t)i * DD;

    // mu = 0..2: periodic rolls on t/z/y (bit fields at shift 11/7/3, width 4)
#pragma unroll 1
    for (int mu = 0; mu < 3; ++mu) {
        const int sh = 11 - 4 * mu;
        const int c = (site >> sh) & 15;
        const int base = site & ~(15 << sh);
        const int nf = base | (((c + 1) & 15) << sh);
        const int nb = base | (((c + 15) & 15) << sh);
        const size_t ko = (size_t)mu * KSTRIDE + rowoff;
        cmatvec_row(Kfr + ko, Kfi + ko,
                    psr + (size_t)nf * DD, psi + (size_t)nf * DD,
                    hr0, hi0, hr1, hi1);
        cmatvec_row(Kbr + ko, Kbi + ko,
                    psr + (size_t)nb * DD, psi + (size_t)nb * DD,
                    hr0, hi0, hr1, hi1);
    }

    // mu = 3: staggered X hop gated by r=(t+z+y)&1 (fwd iff r==1, bwd iff r==0)
    {
        const int x = site & 7;
        const int r = ((site >> 3) + (site >> 7) + (site >> 11)) & 1;
        const int nXf = r ? ((site & ~7) | ((x + 1) & 7)) : site;
        const int nXb = r ? site : ((site & ~7) | ((x + 7) & 7));
        const size_t ko = 3 * KSTRIDE + rowoff;
        cmatvec_row(Kfr + ko, Kfi + ko,
                    psr + (size_t)nXf * DD, psi + (size_t)nXf * DD,
                    hr0, hi0, hr1, hi1);
        cmatvec_row(Kbr + ko, Kbi + ko,
                    psr + (size_t)nXb * DD, psi + (size_t)nXb * DD,
                    hr0, hi0, hr1, hi1);
    }

    const size_t so = (size_t)site * DD + i;
    const float pre = __ldg(psr + so);
    const float pim = __ldg(psi + so);
    out[so]                   = DIAGC * pre - 0.5f * (hr0 + hr1);
    out[(size_t)NV * DD + so] = DIAGC * pim - 0.5f * (hi0 + hi1);
}

extern "C" void kernel_launch(void* const* d_in, const int* in_sizes, int n_in,
                              void* d_out, int out_size)
{
    const float* psr = (const float*)d_in[0];
    const float* psi = (const float*)d_in[1];
    const float* Kfr = (const float*)d_in[2];
    const float* Kfi = (const float*)d_in[3];
    const float* Kbr = (const float*)d_in[4];
    const float* Kbi = (const float*)d_in[5];
    float* out = (float*)d_out;

    dim3 block(12, 16);      // 12 rows x 16 sites = 192 threads
    dim3 grid(NV / 16);      // 2048 blocks
    hop_kernel<<<grid, block>>>(psr, psi, Kfr, Kfi, Kbr, Kbi, out);
}

// round 3
// speedup vs baseline: 1.1219x; 1.1219x over previous
#include <cuda_runtime.h>

// Half-lattice hop operator:
//   out = DIAG*psi - 0.5 * sum_mu ( K_fwd[mu] @ psi(fwd nbr) + K_bwd[mu] @ psi(bwd nbr) )
// T=Z=Y=16, X/2=8, D=12 complex. mu<3: periodic roll on t/z/y; mu=3: parity-gated X hop.

#define DD 12
#define NV (16*16*16*8)   // 32768 sites
#define DIAGC 4.5f
#define KSTRIDE (NV * DD * DD)   // 4718592 floats, fits u32

__device__ __forceinline__ void cmatvec_row(
    const float* __restrict__ Krb, const float* __restrict__ Kib, unsigned ko,
    const float* __restrict__ prb, const float* __restrict__ pib, unsigned po,
    float& hr0, float& hi0, float& hr1, float& hi1)
{
    const float4* kr4 = reinterpret_cast<const float4*>(Krb + ko);
    const float4* ki4 = reinterpret_cast<const float4*>(Kib + ko);
    const float4* pr4 = reinterpret_cast<const float4*>(prb + po);
    const float4* pi4 = reinterpret_cast<const float4*>(pib + po);
#pragma unroll
    for (int c = 0; c < 3; ++c) {
        float4 kr = __ldg(kr4 + c);
        float4 ki = __ldg(ki4 + c);
        float4 vr = __ldg(pr4 + c);
        float4 vi = __ldg(pi4 + c);
        hr0 = fmaf(kr.x, vr.x, hr0); hr0 = fmaf(-ki.x, vi.x, hr0);
        hi0 = fmaf(kr.x, vi.x, hi0); hi0 = fmaf( ki.x, vr.x, hi0);
        hr1 = fmaf(kr.y, vr.y, hr1); hr1 = fmaf(-ki.y, vi.y, hr1);
        hi1 = fmaf(kr.y, vi.y, hi1); hi1 = fmaf( ki.y, vr.y, hi1);
        hr0 = fmaf(kr.z, vr.z, hr0); hr0 = fmaf(-ki.z, vi.z, hr0);
        hi0 = fmaf(kr.z, vi.z, hi0); hi0 = fmaf( ki.z, vr.z, hi0);
        hr1 = fmaf(kr.w, vr.w, hr1); hr1 = fmaf(-ki.w, vi.w, hr1);
        hi1 = fmaf(kr.w, vi.w, hi1); hi1 = fmaf( ki.w, vr.w, hi1);
    }
}

__global__ __launch_bounds__(192)
void hop_kernel(const float* __restrict__ psr, const float* __restrict__ psi,
                const float* __restrict__ Kfr, const float* __restrict__ Kfi,
                const float* __restrict__ Kbr, const float* __restrict__ Kbi,
                float* __restrict__ out)
{
    const int site = blockIdx.x * 16 + threadIdx.y;
    const int i = threadIdx.x;   // 0..11, output row

    // site bits: x [0:3), y [3:7), z [7:11), t [11:15)
    const int x = site & 7;
    const int y = (site >> 3) & 15;
    const int z = (site >> 7) & 15;
    const int t = (site >> 11) & 15;

    const int nTf = (site & ~(15 << 11)) | (((t + 1) & 15) << 11);
    const int nTb = (site & ~(15 << 11)) | (((t + 15) & 15) << 11);
    const int nZf = (site & ~(15 << 7))  | (((z + 1) & 15) << 7);
    const int nZb = (site & ~(15 << 7))  | (((z + 15) & 15) << 7);
    const int nYf = (site & ~(15 << 3))  | (((y + 1) & 15) << 3);
    const int nYb = (site & ~(15 << 3))  | (((y + 15) & 15) << 3);
    const int r = (t + z + y) & 1;
    const int nXf = r ? ((site & ~7) | ((x + 1) & 7)) : site;    // fwd hop iff r==1
    const int nXb = r ? site : ((site & ~7) | ((x + 7) & 7));    // bwd hop iff r==0

    const unsigned nf[4] = {(unsigned)nTf * DD, (unsigned)nZf * DD,
                            (unsigned)nYf * DD, (unsigned)nXf * DD};
    const unsigned nb[4] = {(unsigned)nTb * DD, (unsigned)nZb * DD,
                            (unsigned)nYb * DD, (unsigned)nXb * DD};

    float hr0 = 0.f, hi0 = 0.f, hr1 = 0.f, hi1 = 0.f;
    const unsigned rowoff = (unsigned)site * (DD * DD) + (unsigned)i * DD;

#pragma unroll
    for (int mu = 0; mu < 4; ++mu) {
        const unsigned ko = (unsigned)mu * KSTRIDE + rowoff;
        cmatvec_row(Kfr, Kfi, ko, psr, psi, nf[mu], hr0, hi0, hr1, hi1);
        cmatvec_row(Kbr, Kbi, ko, psr, psi, nb[mu], hr0, hi0, hr1, hi1);
    }

    const unsigned so = (unsigned)site * DD + (unsigned)i;
    const float pre = __ldg(psr + so);
    const float pim = __ldg(psi + so);
    out[so]                = DIAGC * pre - 0.5f * (hr0 + hr1);
    out[NV * DD + so]      = DIAGC * pim - 0.5f * (hi0 + hi1);
}

extern "C" void kernel_launch(void* const* d_in, const int* in_sizes, int n_in,
                              void* d_out, int out_size)
{
    const float* psr = (const float*)d_in[0];
    const float* psi = (const float*)d_in[1];
    const float* Kfr = (const float*)d_in[2];
    const float* Kfi = (const float*)d_in[3];
    const float* Kbr = (const float*)d_in[4];
    const float* Kbi = (const float*)d_in[5];
    float* out = (float*)d_out;

    dim3 block(12, 16);      // 12 rows x 16 sites = 192 threads
    dim3 grid(NV / 16);      // 2048 blocks
    hop_kernel<<<grid, block>>>(psr, psi, Kfr, Kfi, Kbr, Kbi, out);
}